// round 9
// baseline (speedup 1.0000x reference)
#include <cuda_runtime.h>
#include <cuda_bf16.h>
#include <cstdint>

#define BB 2
#define CC 32
#define DD 16
#define CKK 4
#define EE 64      // CKK*DD
#define MM 512     // CC*DD
#define NN 4096    // H*W

// ---------------- scratch (allocation-free device globals) -----------------
__device__ __align__(128) __nv_bfloat16 g_K[BB*NN*EE];         // [b][i][e]
__device__ __align__(128) __nv_bfloat16 g_Q[BB*NN*EE];         // [b][j][e]
__device__ __align__(128) __nv_bfloat16 g_V[BB*MM*NN];         // [b][m][j]
__device__ __align__(128) __nv_bfloat16 g_P[(size_t)BB*NN*NN]; // [b][i][j] 64MB
__device__ __align__(128) float g_rsum[BB*4*NN];               // [b][quarter][i]

// ---------------- helpers ---------------------------------------------------
__device__ __forceinline__ uint32_t smem_u32(const void* p) {
    uint32_t a;
    asm("{ .reg .u64 t; cvta.to.shared.u64 t, %1; cvt.u32.u64 %0, t; }"
        : "=r"(a) : "l"(p));
    return a;
}
// swizzled byte offset for (row, 16B-chunk) in a 128B-row tile
__device__ __forceinline__ uint32_t swoff(int r, int c) {
    return (uint32_t)(r * 128 + ((c ^ (r & 7)) << 4));
}
__device__ __forceinline__ void ldm_x4(uint32_t* r, uint32_t addr) {
    asm volatile("ldmatrix.sync.aligned.m8n8.x4.shared.b16 {%0,%1,%2,%3}, [%4];"
        : "=r"(r[0]), "=r"(r[1]), "=r"(r[2]), "=r"(r[3]) : "r"(addr));
}
__device__ __forceinline__ void mma_bf16(float* c, const uint32_t* a, const uint32_t* b) {
    asm volatile("mma.sync.aligned.m16n8k16.row.col.f32.bf16.bf16.f32 "
        "{%0,%1,%2,%3}, {%4,%5,%6,%7}, {%8,%9}, {%0,%1,%2,%3};"
        : "+f"(c[0]), "+f"(c[1]), "+f"(c[2]), "+f"(c[3])
        : "r"(a[0]), "r"(a[1]), "r"(a[2]), "r"(a[3]), "r"(b[0]), "r"(b[1]));
}
__device__ __forceinline__ void cpasync16(uint32_t dst, const void* src) {
    asm volatile("cp.async.cg.shared.global [%0], [%1], 16;" :: "r"(dst), "l"(src));
}
// fast exp: e^x = 2^(x*log2e), deg-4 poly, rel err ~5e-5
__device__ __forceinline__ float fast_exp(float x) {
    float t  = x * 1.4426950408889634f;
    float rn = (t + 12582912.0f) - 12582912.0f;
    float f  = t - rn;
    int   n  = (int)rn;
    float p = 0.00961812910762848f;
    p = fmaf(p, f, 0.0555041086648216f);
    p = fmaf(p, f, 0.2402265069591007f);
    p = fmaf(p, f, 0.6931471805599453f);
    p = fmaf(p, f, 1.0f);
    return __int_as_float(__float_as_int(p) + (n << 23));
}

// ---------------------------------------------------------------------------
// Projection v3: CTA = (b, 8-d group, 32-i chunk); phase-specific thread maps
// so K/Q stores are 16B-contiguous segments and V stores stay coalesced.
// grid BB*2*128 = 512 CTAs, 256 threads.
// ---------------------------------------------------------------------------
#define SXS 36                 // padded i-stride per dl (bank-conflict-free)

__global__ __launch_bounds__(256) void rsa_proj_kernel(
    const float* __restrict__ x,
    const float* __restrict__ Wk, const float* __restrict__ bk,
    const float* __restrict__ Wq, const float* __restrict__ bq,
    const float* __restrict__ Wv, const float* __restrict__ bv)
{
    __shared__ float sX[CC*8*SXS];               // [c][dl][i] 36864B
    __shared__ float sWk[CKK*CC], sWq[CKK*CC], sWv[CC*CC];
    __shared__ float sbk[CKK], sbq[CKK], sbv[CC];
    const int tid = threadIdx.x;
    for (int t = tid; t < CKK*CC; t += 256) { sWk[t] = Wk[t]; sWq[t] = Wq[t]; }
    for (int t = tid; t < CC*CC; t += 256) sWv[t] = Wv[t];
    if (tid < CKK) { sbk[tid] = bk[tid]; sbq[tid] = bq[tid]; }
    if (tid < CC)  sbv[tid] = bv[tid];

    const int blk   = blockIdx.x;
    const int chunk = blk & 127;
    const int d8    = (blk >> 7) & 1;
    const int b     = blk >> 8;
    const int ibase = chunk * 32;

    // coalesced x tile load: [32 c][8 dl][32 i]
    {
        const int dl = tid >> 5, i = tid & 31;
        const float* xp = x + ((size_t)(b*CC)*DD + d8*8 + dl)*NN + ibase + i;
#pragma unroll
        for (int c = 0; c < CC; c++)
            sX[c*(8*SXS) + dl*SXS + i] = xp[(size_t)c*DD*NN];
    }
    __syncthreads();

    // K/Q phase: thread = (i = tid>>3, dl = tid&7)
    {
        const int i = tid >> 3, dl = tid & 7;
        float ka[CKK], qa[CKK];
#pragma unroll
        for (int o = 0; o < CKK; o++) { ka[o] = sbk[o]; qa[o] = sbq[o]; }
#pragma unroll
        for (int c = 0; c < CC; c++) {
            float xv = sX[c*(8*SXS) + dl*SXS + i];
#pragma unroll
            for (int o = 0; o < CKK; o++) {
                ka[o] = fmaf(sWk[o*CC + c], xv, ka[o]);
                qa[o] = fmaf(sWq[o*CC + c], xv, qa[o]);
            }
        }
#pragma unroll
        for (int o = 0; o < CKK; o++) {
            int e = o*DD + d8*8 + dl;
            g_K[(size_t)(b*NN + ibase + i)*EE + e] = __float2bfloat16_rn(ka[o]);
            g_Q[(size_t)(b*NN + ibase + i)*EE + e] = __float2bfloat16_rn(qa[o]);
        }
    }

    // V phase: thread = (dl = tid>>5, i = tid&31) -> fully coalesced stores
    {
        const int dl = tid >> 5, i = tid & 31;
#pragma unroll
        for (int gr = 0; gr < 4; gr++) {
            float va[8];
#pragma unroll
            for (int o = 0; o < 8; o++) va[o] = sbv[gr*8 + o];
#pragma unroll
            for (int c = 0; c < CC; c++) {
                float xv = sX[c*(8*SXS) + dl*SXS + i];
#pragma unroll
                for (int o = 0; o < 8; o++)
                    va[o] = fmaf(sWv[(gr*8 + o)*CC + c], xv, va[o]);
            }
#pragma unroll
            for (int o = 0; o < 8; o++) {
                int m = (gr*8 + o)*DD + d8*8 + dl;
                g_V[((size_t)(b*MM + m))*NN + ibase + i] = __float2bfloat16_rn(va[o]);
            }
        }
    }
}

// ---------------------------------------------------------------------------
// QK kernel: S = K_i Q_j^T (mma.sync bf16), P = exp(S) -> g_P, row partials.
// grid (32 i-tiles, 4 j-quarters, BB), 256 threads (8 warps x 16 i-rows)
// ---------------------------------------------------------------------------
#define QK_SM_K 0
#define QK_SM_Q 16384
#define QK_SM_P 32768                      // uint32[128][68]
#define QK_SMEM (32768 + 128*68*4)         // 67584

__global__ __launch_bounds__(256, 2) void rsa_qk_kernel()
{
    extern __shared__ char smem[];
    const uint32_t sb = smem_u32(smem);
    uint32_t* sP = (uint32_t*)(smem + QK_SM_P);
    const int tid  = threadIdx.x;
    const int wid  = tid >> 5, lane = tid & 31;
    const int g    = lane >> 2, q = lane & 3;
    const int b    = blockIdx.z, ibase = blockIdx.x * 128, quart = blockIdx.y;
    const int wbase = wid * 16;

    for (int f = tid; f < 1024; f += 256) {
        int r = f >> 3, c = f & 7;
        *(float4*)(smem + QK_SM_K + swoff(r, c)) =
            *(const float4*)(g_K + (size_t)(b*NN + ibase + r)*EE + c*8);
    }
    __syncthreads();

    uint32_t afr[4][4];
    {
        int sg = lane >> 3, rr = lane & 7;
        int arow = wbase + ((sg & 1) << 3) + rr;
#pragma unroll
        for (int ks = 0; ks < 4; ks++)
            ldm_x4(afr[ks], sb + QK_SM_K + swoff(arow, 2*ks + (sg >> 1)));
    }

    const int brow = lane & 7, bco = lane >> 3;
    float rs0 = 0.f, rs1 = 0.f;

    for (int jt = 0; jt < 8; jt++) {
        const int jb = quart*1024 + jt*128;
        __syncthreads();
        for (int f = tid; f < 1024; f += 256) {
            int r = f >> 3, c = f & 7;
            *(float4*)(smem + QK_SM_Q + swoff(r, c)) =
                *(const float4*)(g_Q + (size_t)(b*NN + jb + r)*EE + c*8);
        }
        __syncthreads();

#pragma unroll
        for (int f = 0; f < 16; f++) {
            float acc[4] = {0.f, 0.f, 0.f, 0.f};
            uint32_t bfr[8];
            ldm_x4(bfr,     sb + QK_SM_Q + swoff(f*8 + brow, 0 + bco));
            ldm_x4(bfr + 4, sb + QK_SM_Q + swoff(f*8 + brow, 4 + bco));
            mma_bf16(acc, afr[0], bfr);
            mma_bf16(acc, afr[1], bfr + 2);
            mma_bf16(acc, afr[2], bfr + 4);
            mma_bf16(acc, afr[3], bfr + 6);
            float e0 = fast_exp(acc[0]), e1 = fast_exp(acc[1]);
            float e2 = fast_exp(acc[2]), e3 = fast_exp(acc[3]);
            rs0 += e0 + e1; rs1 += e2 + e3;
            __nv_bfloat162 h0 = __floats2bfloat162_rn(e0, e1);
            __nv_bfloat162 h1 = __floats2bfloat162_rn(e2, e3);
            sP[(wbase + g    )*68 + f*4 + q] = *(uint32_t*)&h0;
            sP[(wbase + g + 8)*68 + f*4 + q] = *(uint32_t*)&h1;
        }
        __syncthreads();
        for (int f = tid; f < 8192; f += 256) {
            int r = f >> 6, c = f & 63;
            ((uint32_t*)(g_P + (size_t)(b*NN + ibase + r)*NN + jb))[c] = sP[r*68 + c];
        }
    }

    rs0 += __shfl_xor_sync(0xffffffffu, rs0, 1);
    rs0 += __shfl_xor_sync(0xffffffffu, rs0, 2);
    rs1 += __shfl_xor_sync(0xffffffffu, rs1, 1);
    rs1 += __shfl_xor_sync(0xffffffffu, rs1, 2);
    if (q == 0) {
        g_rsum[(b*4 + quart)*NN + ibase + wbase + g]     = rs0;
        g_rsum[(b*4 + quart)*NN + ibase + wbase + g + 8] = rs1;
    }
}

// ---------------------------------------------------------------------------
// PV kernel: D[128i,128m] = sum_j P[i,j] V[m,j]; normalize + residual.
// 2D warp tiling (4 i-warps x 2 m-warps): smem traffic 144->96 KB/chunk.
// 2-stage double buffer (R4/R6-proven ordering).
// grid (32 i-tiles, 4 m-tiles, BB), 256 threads
// ---------------------------------------------------------------------------
#define PV_A0 0
#define PV_A1 16384
#define PV_B0 32768
#define PV_B1 49152
#define PV_SINV (128*132*4)                 // 67584 (sO occupies [0,67584))
#define PV_SMEM (PV_SINV + 512)

__global__ __launch_bounds__(256, 2) void rsa_pv_kernel(
    const float* __restrict__ x,
    const float* __restrict__ gamma,
    float* __restrict__ out)
{
    extern __shared__ char smem[];
    const uint32_t sb = smem_u32(smem);
    const int tid  = threadIdx.x;
    const int wid  = tid >> 5, lane = tid & 31;
    const int g    = lane >> 2, q = lane & 3;
    const int b    = blockIdx.z, ibase = blockIdx.x * 128, mbase = blockIdx.y * 128;
    const int wi   = wid & 3;          // i-group: rows wi*32 .. +31
    const int wm   = wid >> 2;         // m-half:  cols wm*64 .. +63

    const uint32_t smA[2] = { sb + PV_A0, sb + PV_A1 };
    const uint32_t smB[2] = { sb + PV_B0, sb + PV_B1 };

    auto load_chunk = [&](int c, int p) {
        const int jb = c * 64;
#pragma unroll
        for (int it = 0; it < 4; it++) {
            int f = it*256 + tid;
            int r = f >> 3, cc = f & 7;
            uint32_t off = swoff(r, cc);
            cpasync16(smA[p] + off, g_P + (size_t)(b*NN + ibase + r)*NN + jb + cc*8);
            cpasync16(smB[p] + off, g_V + (size_t)(b*MM + mbase + r)*NN + jb + cc*8);
        }
        asm volatile("cp.async.commit_group;" ::: "memory");
    };

    float acc[2][8][4];
#pragma unroll
    for (int it = 0; it < 2; it++)
#pragma unroll
        for (int f = 0; f < 8; f++)
            acc[it][f][0] = acc[it][f][1] = acc[it][f][2] = acc[it][f][3] = 0.f;

    load_chunk(0, 0);

    const int sg = lane >> 3, rr = lane & 7;
    const int brow = lane & 7, bco = lane >> 3;

    for (int c = 0; c < 64; c++) {
        const int p = c & 1;
        if (c + 1 < 64) {
            load_chunk(c + 1, p ^ 1);
            asm volatile("cp.async.wait_group 1;" ::: "memory");
        } else {
            asm volatile("cp.async.wait_group 0;" ::: "memory");
        }
        __syncthreads();

        uint32_t afr[2][4][4];
#pragma unroll
        for (int it = 0; it < 2; it++) {
            int arow = wi*32 + it*16 + ((sg & 1) << 3) + rr;
#pragma unroll
            for (int ks = 0; ks < 4; ks++)
                ldm_x4(afr[it][ks], smA[p] + swoff(arow, 2*ks + (sg >> 1)));
        }
#pragma unroll
        for (int f = 0; f < 8; f++) {
            uint32_t bfr[8];
            ldm_x4(bfr,     smB[p] + swoff(wm*64 + f*8 + brow, 0 + bco));
            ldm_x4(bfr + 4, smB[p] + swoff(wm*64 + f*8 + brow, 4 + bco));
#pragma unroll
            for (int it = 0; it < 2; it++) {
                mma_bf16(acc[it][f], afr[it][0], bfr);
                mma_bf16(acc[it][f], afr[it][1], bfr + 2);
                mma_bf16(acc[it][f], afr[it][2], bfr + 4);
                mma_bf16(acc[it][f], afr[it][3], bfr + 6);
            }
        }
        __syncthreads();
    }

    // epilogue: rowsum inverses + stage D into smem (reuses A/B buffers)
    float* sO   = (float*)smem;                 // [128 m][132]
    float* sInv = (float*)(smem + PV_SINV);     // [128]
    if (tid < 128) {
        int i = ibase + tid;
        float rs = g_rsum[(b*4 + 0)*NN + i] + g_rsum[(b*4 + 1)*NN + i]
                 + g_rsum[(b*4 + 2)*NN + i] + g_rsum[(b*4 + 3)*NN + i];
        sInv[tid] = 1.0f / rs;
    }
#pragma unroll
    for (int it = 0; it < 2; it++) {
#pragma unroll
        for (int f = 0; f < 8; f++) {
            int m0 = wm*64 + f*8 + q*2;
            int il = wi*32 + it*16;
            sO[(m0    )*132 + il + g]     = acc[it][f][0];
            sO[(m0 + 1)*132 + il + g]     = acc[it][f][1];
            sO[(m0    )*132 + il + g + 8] = acc[it][f][2];
            sO[(m0 + 1)*132 + il + g + 8] = acc[it][f][3];
        }
    }
    __syncthreads();

    const float gm = gamma[0];
    for (int idx = tid; idx < 128*128; idx += 256) {
        int m = idx >> 7, i = idx & 127;
        size_t gi = (size_t)(b*MM + mbase + m)*NN + ibase + i;
        out[gi] = gm * x[gi] + sO[m*132 + i] * sInv[i];
    }
}

// ---------------------------------------------------------------------------
extern "C" void kernel_launch(void* const* d_in, const int* in_sizes, int n_in,
                              void* d_out, int out_size)
{
    const float* x     = (const float*)d_in[0];
    const float* Wk    = (const float*)d_in[1];
    const float* bk    = (const float*)d_in[2];
    const float* Wq    = (const float*)d_in[3];
    const float* bq    = (const float*)d_in[4];
    const float* Wv    = (const float*)d_in[5];
    const float* bv    = (const float*)d_in[6];
    const float* gamma = (const float*)d_in[7];
    float* out = (float*)d_out;

    cudaFuncSetAttribute(rsa_qk_kernel,
                         cudaFuncAttributeMaxDynamicSharedMemorySize, QK_SMEM);
    cudaFuncSetAttribute(rsa_pv_kernel,
                         cudaFuncAttributeMaxDynamicSharedMemorySize, PV_SMEM);

    rsa_proj_kernel<<<BB*2*128, 256>>>(x, Wk, bk, Wq, bq, Wv, bv);

    dim3 gqk(32, 4, BB);
    rsa_qk_kernel<<<gqk, 256, QK_SMEM>>>();

    dim3 gpv(32, 4, BB);
    rsa_pv_kernel<<<gpv, 256, PV_SMEM>>>(x, gamma, out);
}

// round 11
// speedup vs baseline: 1.5131x; 1.5131x over previous
#include <cuda_runtime.h>
#include <cuda_bf16.h>
#include <cstdint>

#define BB 2
#define CC 32
#define DD 16
#define CKK 4
#define EE 64      // CKK*DD
#define MM 512     // CC*DD
#define NN 4096    // H*W

// ---------------- scratch (allocation-free device globals) -----------------
__device__ __align__(128) __nv_bfloat16 g_K[BB*NN*EE];         // [b][i][e]
__device__ __align__(128) __nv_bfloat16 g_Q[BB*NN*EE];         // [b][j][e]
__device__ __align__(128) __nv_bfloat16 g_V[BB*MM*NN];         // [b][m][j]
__device__ __align__(128) __nv_bfloat16 g_P[(size_t)BB*NN*NN]; // [b][i][j] 64MB
__device__ __align__(128) float g_rsum[BB*4*NN];               // [b][quarter][i]

// ---------------- helpers ---------------------------------------------------
__device__ __forceinline__ uint32_t smem_u32(const void* p) {
    uint32_t a;
    asm("{ .reg .u64 t; cvta.to.shared.u64 t, %1; cvt.u32.u64 %0, t; }"
        : "=r"(a) : "l"(p));
    return a;
}
// swizzled byte offset for (row, 16B-chunk) in a 128B-row tile
__device__ __forceinline__ uint32_t swoff(int r, int c) {
    return (uint32_t)(r * 128 + ((c ^ (r & 7)) << 4));
}
__device__ __forceinline__ void ldm_x4(uint32_t* r, uint32_t addr) {
    asm volatile("ldmatrix.sync.aligned.m8n8.x4.shared.b16 {%0,%1,%2,%3}, [%4];"
        : "=r"(r[0]), "=r"(r[1]), "=r"(r[2]), "=r"(r[3]) : "r"(addr));
}
__device__ __forceinline__ void ldm_x2(uint32_t* r, uint32_t addr) {
    asm volatile("ldmatrix.sync.aligned.m8n8.x2.shared.b16 {%0,%1}, [%2];"
        : "=r"(r[0]), "=r"(r[1]) : "r"(addr));
}
__device__ __forceinline__ void mma_bf16(float* c, const uint32_t* a, const uint32_t* b) {
    asm volatile("mma.sync.aligned.m16n8k16.row.col.f32.bf16.bf16.f32 "
        "{%0,%1,%2,%3}, {%4,%5,%6,%7}, {%8,%9}, {%0,%1,%2,%3};"
        : "+f"(c[0]), "+f"(c[1]), "+f"(c[2]), "+f"(c[3])
        : "r"(a[0]), "r"(a[1]), "r"(a[2]), "r"(a[3]), "r"(b[0]), "r"(b[1]));
}
__device__ __forceinline__ void cpasync16(uint32_t dst, const void* src) {
    asm volatile("cp.async.cg.shared.global [%0], [%1], 16;" :: "r"(dst), "l"(src));
}
// fast exp: e^x = 2^(x*log2e), deg-4 poly, rel err ~5e-5
__device__ __forceinline__ float fast_exp(float x) {
    float t  = x * 1.4426950408889634f;
    float rn = (t + 12582912.0f) - 12582912.0f;
    float f  = t - rn;
    int   n  = (int)rn;
    float p = 0.00961812910762848f;
    p = fmaf(p, f, 0.0555041086648216f);
    p = fmaf(p, f, 0.2402265069591007f);
    p = fmaf(p, f, 0.6931471805599453f);
    p = fmaf(p, f, 1.0f);
    return __int_as_float(__float_as_int(p) + (n << 23));
}

// ---------------------------------------------------------------------------
// Projection v2 (R6-proven): smem-staged x tile, low-register groups.
// grid BB*DD*16 (512 CTAs), 256 threads.
// ---------------------------------------------------------------------------
__global__ __launch_bounds__(256) void rsa_proj_kernel(
    const float* __restrict__ x,
    const float* __restrict__ Wk, const float* __restrict__ bk,
    const float* __restrict__ Wq, const float* __restrict__ bq,
    const float* __restrict__ Wv, const float* __restrict__ bv)
{
    __shared__ float sX[CC*256];
    __shared__ float sWk[CKK*CC], sWq[CKK*CC], sWv[CC*CC];
    __shared__ float sbk[CKK], sbq[CKK], sbv[CC];
    const int tid = threadIdx.x;
    for (int t = tid; t < CKK*CC; t += 256) { sWk[t] = Wk[t]; sWq[t] = Wq[t]; }
    for (int t = tid; t < CC*CC; t += 256) sWv[t] = Wv[t];
    if (tid < CKK) { sbk[tid] = bk[tid]; sbq[tid] = bq[tid]; }
    if (tid < CC)  sbv[tid] = bv[tid];

    const int blk   = blockIdx.x;
    const int chunk = blk & 15;
    const int d     = (blk >> 4) & 15;
    const int b     = blk >> 8;
    const int ibase = chunk * 256;

#pragma unroll
    for (int f = 0; f < CC; f++)
        sX[f*256 + tid] = x[((size_t)(b*CC + f)*DD + d)*NN + ibase + tid];
    __syncthreads();

    const int i = tid;

    {
        float ka[CKK], qa[CKK];
#pragma unroll
        for (int o = 0; o < CKK; o++) { ka[o] = sbk[o]; qa[o] = sbq[o]; }
#pragma unroll
        for (int c = 0; c < CC; c++) {
            float xv = sX[c*256 + i];
#pragma unroll
            for (int o = 0; o < CKK; o++) {
                ka[o] = fmaf(sWk[o*CC + c], xv, ka[o]);
                qa[o] = fmaf(sWq[o*CC + c], xv, qa[o]);
            }
        }
#pragma unroll
        for (int o = 0; o < CKK; o++) {
            g_K[(size_t)(b*NN + ibase + i)*EE + o*DD + d] = __float2bfloat16_rn(ka[o]);
            g_Q[(size_t)(b*NN + ibase + i)*EE + o*DD + d] = __float2bfloat16_rn(qa[o]);
        }
    }

#pragma unroll
    for (int gr = 0; gr < 4; gr++) {
        float va[8];
#pragma unroll
        for (int o = 0; o < 8; o++) va[o] = sbv[gr*8 + o];
#pragma unroll
        for (int c = 0; c < CC; c++) {
            float xv = sX[c*256 + i];
#pragma unroll
            for (int o = 0; o < 8; o++)
                va[o] = fmaf(sWv[(gr*8 + o)*CC + c], xv, va[o]);
        }
#pragma unroll
        for (int o = 0; o < 8; o++)
            g_V[((size_t)(b*MM + (gr*8 + o)*DD + d))*NN + ibase + i] =
                __float2bfloat16_rn(va[o]);
    }
}

// ---------------------------------------------------------------------------
// QK kernel (R6-proven): S = K_i Q_j^T, P = exp(S) -> g_P, row partials.
// grid (32 i-tiles, 4 j-quarters, BB), 256 threads
// ---------------------------------------------------------------------------
#define QK_SM_K 0
#define QK_SM_Q 16384
#define QK_SM_P 32768                      // uint32[128][68]
#define QK_SMEM (32768 + 128*68*4)         // 67584

__global__ __launch_bounds__(256, 2) void rsa_qk_kernel()
{
    extern __shared__ char smem[];
    const uint32_t sb = smem_u32(smem);
    uint32_t* sP = (uint32_t*)(smem + QK_SM_P);
    const int tid  = threadIdx.x;
    const int wid  = tid >> 5, lane = tid & 31;
    const int g    = lane >> 2, q = lane & 3;
    const int b    = blockIdx.z, ibase = blockIdx.x * 128, quart = blockIdx.y;
    const int wbase = wid * 16;

    for (int f = tid; f < 1024; f += 256) {
        int r = f >> 3, c = f & 7;
        *(float4*)(smem + QK_SM_K + swoff(r, c)) =
            *(const float4*)(g_K + (size_t)(b*NN + ibase + r)*EE + c*8);
    }
    __syncthreads();

    uint32_t afr[4][4];
    {
        int sg = lane >> 3, rr = lane & 7;
        int arow = wbase + ((sg & 1) << 3) + rr;
#pragma unroll
        for (int ks = 0; ks < 4; ks++)
            ldm_x4(afr[ks], sb + QK_SM_K + swoff(arow, 2*ks + (sg >> 1)));
    }

    const int brow = lane & 7, bco = lane >> 3;
    float rs0 = 0.f, rs1 = 0.f;

    for (int jt = 0; jt < 8; jt++) {
        const int jb = quart*1024 + jt*128;
        __syncthreads();
        for (int f = tid; f < 1024; f += 256) {
            int r = f >> 3, c = f & 7;
            *(float4*)(smem + QK_SM_Q + swoff(r, c)) =
                *(const float4*)(g_Q + (size_t)(b*NN + jb + r)*EE + c*8);
        }
        __syncthreads();

#pragma unroll
        for (int f = 0; f < 16; f++) {
            float acc[4] = {0.f, 0.f, 0.f, 0.f};
            uint32_t bfr[8];
            ldm_x4(bfr,     sb + QK_SM_Q + swoff(f*8 + brow, 0 + bco));
            ldm_x4(bfr + 4, sb + QK_SM_Q + swoff(f*8 + brow, 4 + bco));
            mma_bf16(acc, afr[0], bfr);
            mma_bf16(acc, afr[1], bfr + 2);
            mma_bf16(acc, afr[2], bfr + 4);
            mma_bf16(acc, afr[3], bfr + 6);
            float e0 = fast_exp(acc[0]), e1 = fast_exp(acc[1]);
            float e2 = fast_exp(acc[2]), e3 = fast_exp(acc[3]);
            rs0 += e0 + e1; rs1 += e2 + e3;
            __nv_bfloat162 h0 = __floats2bfloat162_rn(e0, e1);
            __nv_bfloat162 h1 = __floats2bfloat162_rn(e2, e3);
            sP[(wbase + g    )*68 + f*4 + q] = *(uint32_t*)&h0;
            sP[(wbase + g + 8)*68 + f*4 + q] = *(uint32_t*)&h1;
        }
        __syncthreads();
        for (int f = tid; f < 8192; f += 256) {
            int r = f >> 6, c = f & 63;
            ((uint32_t*)(g_P + (size_t)(b*NN + ibase + r)*NN + jb))[c] = sP[r*68 + c];
        }
    }

    rs0 += __shfl_xor_sync(0xffffffffu, rs0, 1);
    rs0 += __shfl_xor_sync(0xffffffffu, rs0, 2);
    rs1 += __shfl_xor_sync(0xffffffffu, rs1, 1);
    rs1 += __shfl_xor_sync(0xffffffffu, rs1, 2);
    if (q == 0) {
        g_rsum[(b*4 + quart)*NN + ibase + wbase + g]     = rs0;
        g_rsum[(b*4 + quart)*NN + ibase + wbase + g + 8] = rs1;
    }
}

// ---------------------------------------------------------------------------
// PV kernel: D[128i,128m] = sum_j P[i,j] V[m,j]; normalize + residual.
// Warp tile 64i x 32m (2 i-warps x 4 m-warps); k-step OUTER loop so only ONE
// 16-reg A-fragment set is live at a time (R9 spill fix). Crossbar/chunk:
// 144KB -> 96KB. 2-stage double buffer (R4/R6-proven ordering).
// grid (32 i-tiles, 4 m-tiles, BB), 256 threads
// ---------------------------------------------------------------------------
#define PV_A0 0
#define PV_A1 16384
#define PV_B0 32768
#define PV_B1 49152
#define PV_SINV (128*132*4)                 // 67584 (sO occupies [0,67584))
#define PV_SMEM (PV_SINV + 512)

__global__ __launch_bounds__(256, 2) void rsa_pv_kernel(
    const float* __restrict__ x,
    const float* __restrict__ gamma,
    float* __restrict__ out)
{
    extern __shared__ char smem[];
    const uint32_t sb = smem_u32(smem);
    const int tid  = threadIdx.x;
    const int wid  = tid >> 5, lane = tid & 31;
    const int g    = lane >> 2, q = lane & 3;
    const int b    = blockIdx.z, ibase = blockIdx.x * 128, mbase = blockIdx.y * 128;
    const int wi   = wid & 1;          // i-half:    rows wi*64 .. +63
    const int wm   = wid >> 1;         // m-quarter: cols wm*32 .. +31

    const uint32_t smA[2] = { sb + PV_A0, sb + PV_A1 };
    const uint32_t smB[2] = { sb + PV_B0, sb + PV_B1 };

    auto load_chunk = [&](int c, int p) {
        const int jb = c * 64;
#pragma unroll
        for (int it = 0; it < 4; it++) {
            int f = it*256 + tid;
            int r = f >> 3, cc = f & 7;
            uint32_t off = swoff(r, cc);
            cpasync16(smA[p] + off, g_P + (size_t)(b*NN + ibase + r)*NN + jb + cc*8);
            cpasync16(smB[p] + off, g_V + (size_t)(b*MM + mbase + r)*NN + jb + cc*8);
        }
        asm volatile("cp.async.commit_group;" ::: "memory");
    };

    float acc[4][4][4];                 // [i-subtile][n-group][c-frag]
#pragma unroll
    for (int it = 0; it < 4; it++)
#pragma unroll
        for (int f = 0; f < 4; f++)
            acc[it][f][0] = acc[it][f][1] = acc[it][f][2] = acc[it][f][3] = 0.f;

    load_chunk(0, 0);

    const int sg = lane >> 3, rr = lane & 7;
    const int l16 = lane & 15;                 // x2 address lanes (replicated)
    const int b2row = l16 & 7, b2half = l16 >> 3;

    for (int c = 0; c < 64; c++) {
        const int p = c & 1;
        if (c + 1 < 64) {
            load_chunk(c + 1, p ^ 1);
            asm volatile("cp.async.wait_group 1;" ::: "memory");
        } else {
            asm volatile("cp.async.wait_group 0;" ::: "memory");
        }
        __syncthreads();

#pragma unroll
        for (int ks = 0; ks < 4; ks++) {
            uint32_t afr[4][4];
#pragma unroll
            for (int it = 0; it < 4; it++) {
                int arow = wi*64 + it*16 + ((sg & 1) << 3) + rr;
                ldm_x4(afr[it], smA[p] + swoff(arow, 2*ks + (sg >> 1)));
            }
#pragma unroll
            for (int f = 0; f < 4; f++) {
                uint32_t bfr[2];
                ldm_x2(bfr, smB[p] + swoff(wm*32 + f*8 + b2row, 2*ks + b2half));
#pragma unroll
                for (int it = 0; it < 4; it++)
                    mma_bf16(acc[it][f], afr[it], bfr);
            }
        }
        __syncthreads();
    }

    // epilogue: rowsum inverses + stage D into smem (reuses A/B buffers)
    float* sO   = (float*)smem;                 // [128 m][132]
    float* sInv = (float*)(smem + PV_SINV);     // [128]
    if (tid < 128) {
        int i = ibase + tid;
        float rs = g_rsum[(b*4 + 0)*NN + i] + g_rsum[(b*4 + 1)*NN + i]
                 + g_rsum[(b*4 + 2)*NN + i] + g_rsum[(b*4 + 3)*NN + i];
        sInv[tid] = 1.0f / rs;
    }
#pragma unroll
    for (int it = 0; it < 4; it++) {
#pragma unroll
        for (int f = 0; f < 4; f++) {
            int m0 = wm*32 + f*8 + q*2;
            int il = wi*64 + it*16;
            sO[(m0    )*132 + il + g]     = acc[it][f][0];
            sO[(m0 + 1)*132 + il + g]     = acc[it][f][1];
            sO[(m0    )*132 + il + g + 8] = acc[it][f][2];
            sO[(m0 + 1)*132 + il + g + 8] = acc[it][f][3];
        }
    }
    __syncthreads();

    const float gm = gamma[0];
    for (int idx = tid; idx < 128*128; idx += 256) {
        int m = idx >> 7, i = idx & 127;
        size_t gi = (size_t)(b*MM + mbase + m)*NN + ibase + i;
        out[gi] = gm * x[gi] + sO[m*132 + i] * sInv[i];
    }
}

// ---------------------------------------------------------------------------
extern "C" void kernel_launch(void* const* d_in, const int* in_sizes, int n_in,
                              void* d_out, int out_size)
{
    const float* x     = (const float*)d_in[0];
    const float* Wk    = (const float*)d_in[1];
    const float* bk    = (const float*)d_in[2];
    const float* Wq    = (const float*)d_in[3];
    const float* bq    = (const float*)d_in[4];
    const float* Wv    = (const float*)d_in[5];
    const float* bv    = (const float*)d_in[6];
    const float* gamma = (const float*)d_in[7];
    float* out = (float*)d_out;

    cudaFuncSetAttribute(rsa_qk_kernel,
                         cudaFuncAttributeMaxDynamicSharedMemorySize, QK_SMEM);
    cudaFuncSetAttribute(rsa_pv_kernel,
                         cudaFuncAttributeMaxDynamicSharedMemorySize, PV_SMEM);

    rsa_proj_kernel<<<BB*DD*16, 256>>>(x, Wk, bk, Wq, bq, Wv, bv);

    dim3 gqk(32, 4, BB);
    rsa_qk_kernel<<<gqk, 256, QK_SMEM>>>();

    dim3 gpv(32, 4, BB);
    rsa_pv_kernel<<<gpv, 256, PV_SMEM>>>(x, gamma, out);
}

// round 13
// speedup vs baseline: 1.5563x; 1.0286x over previous
#include <cuda_runtime.h>
#include <cuda_bf16.h>
#include <cstdint>

#define BB 2
#define CC 32
#define DD 16
#define CKK 4
#define EE 64      // CKK*DD
#define MM 512     // CC*DD
#define NN 4096    // H*W

// ---------------- scratch (allocation-free device globals) -----------------
__device__ __align__(128) __nv_bfloat16 g_K[BB*NN*EE];         // [b][i][e]
__device__ __align__(128) __nv_bfloat16 g_Q[BB*NN*EE];         // [b][j][e]
__device__ __align__(128) __nv_bfloat16 g_V[BB*MM*NN];         // [b][m][j]
__device__ __align__(128) __nv_bfloat16 g_P[(size_t)BB*NN*NN]; // [b][i][j] 64MB
__device__ __align__(128) float g_rsum[BB*4*NN];               // [b][quarter][i]

// ---------------- helpers ---------------------------------------------------
__device__ __forceinline__ uint32_t smem_u32(const void* p) {
    uint32_t a;
    asm("{ .reg .u64 t; cvta.to.shared.u64 t, %1; cvt.u32.u64 %0, t; }"
        : "=r"(a) : "l"(p));
    return a;
}
// swizzled byte offset for (row, 16B-chunk) in a 128B-row tile
__device__ __forceinline__ uint32_t swoff(int r, int c) {
    return (uint32_t)(r * 128 + ((c ^ (r & 7)) << 4));
}
__device__ __forceinline__ void ldm_x4(uint32_t* r, uint32_t addr) {
    asm volatile("ldmatrix.sync.aligned.m8n8.x4.shared.b16 {%0,%1,%2,%3}, [%4];"
        : "=r"(r[0]), "=r"(r[1]), "=r"(r[2]), "=r"(r[3]) : "r"(addr));
}
__device__ __forceinline__ void ldm_x2(uint32_t* r, uint32_t addr) {
    asm volatile("ldmatrix.sync.aligned.m8n8.x2.shared.b16 {%0,%1}, [%2];"
        : "=r"(r[0]), "=r"(r[1]) : "r"(addr));
}
__device__ __forceinline__ void mma_bf16(float* c, const uint32_t* a, const uint32_t* b) {
    asm volatile("mma.sync.aligned.m16n8k16.row.col.f32.bf16.bf16.f32 "
        "{%0,%1,%2,%3}, {%4,%5,%6,%7}, {%8,%9}, {%0,%1,%2,%3};"
        : "+f"(c[0]), "+f"(c[1]), "+f"(c[2]), "+f"(c[3])
        : "r"(a[0]), "r"(a[1]), "r"(a[2]), "r"(a[3]), "r"(b[0]), "r"(b[1]));
}
__device__ __forceinline__ void cpasync16(uint32_t dst, const void* src) {
    asm volatile("cp.async.cg.shared.global [%0], [%1], 16;" :: "r"(dst), "l"(src));
}
// fast exp: e^x = 2^(x*log2e), deg-4 poly, rel err ~5e-5
__device__ __forceinline__ float fast_exp(float x) {
    float t  = x * 1.4426950408889634f;
    float rn = (t + 12582912.0f) - 12582912.0f;
    float f  = t - rn;
    int   n  = (int)rn;
    float p = 0.00961812910762848f;
    p = fmaf(p, f, 0.0555041086648216f);
    p = fmaf(p, f, 0.2402265069591007f);
    p = fmaf(p, f, 0.6931471805599453f);
    p = fmaf(p, f, 1.0f);
    return __int_as_float(__float_as_int(p) + (n << 23));
}

// ---------------------------------------------------------------------------
// Projection v4: float4 x-loads (MLP 8), low-register accumulation groups.
// grid BB*DD*16 (512 CTAs), 256 threads.
// ---------------------------------------------------------------------------
__global__ __launch_bounds__(256) void rsa_proj_kernel(
    const float* __restrict__ x,
    const float* __restrict__ Wk, const float* __restrict__ bk,
    const float* __restrict__ Wq, const float* __restrict__ bq,
    const float* __restrict__ Wv, const float* __restrict__ bv)
{
    __shared__ float sX[CC*256];
    __shared__ float sWk[CKK*CC], sWq[CKK*CC], sWv[CC*CC];
    __shared__ float sbk[CKK], sbq[CKK], sbv[CC];
    const int tid = threadIdx.x;
    for (int t = tid; t < CKK*CC; t += 256) { sWk[t] = Wk[t]; sWq[t] = Wq[t]; }
    for (int t = tid; t < CC*CC; t += 256) sWv[t] = Wv[t];
    if (tid < CKK) { sbk[tid] = bk[tid]; sbq[tid] = bq[tid]; }
    if (tid < CC)  sbv[tid] = bv[tid];

    const int blk   = blockIdx.x;
    const int chunk = blk & 15;
    const int d     = (blk >> 4) & 15;
    const int b     = blk >> 8;
    const int ibase = chunk * 256;

    // vectorized coalesced x tile load: 8 independent LDG.128 per thread
    {
        const int cg = tid >> 6;            // 0..3
        const int i4 = (tid & 63) << 2;     // 0..252 step 4
#pragma unroll
        for (int f = 0; f < 8; f++) {
            int c = f*4 + cg;
            *(float4*)&sX[c*256 + i4] =
                *(const float4*)&x[((size_t)(b*CC + c)*DD + d)*NN + ibase + i4];
        }
    }
    __syncthreads();

    const int i = tid;

    {
        float ka[CKK], qa[CKK];
#pragma unroll
        for (int o = 0; o < CKK; o++) { ka[o] = sbk[o]; qa[o] = sbq[o]; }
#pragma unroll
        for (int c = 0; c < CC; c++) {
            float xv = sX[c*256 + i];
#pragma unroll
            for (int o = 0; o < CKK; o++) {
                ka[o] = fmaf(sWk[o*CC + c], xv, ka[o]);
                qa[o] = fmaf(sWq[o*CC + c], xv, qa[o]);
            }
        }
#pragma unroll
        for (int o = 0; o < CKK; o++) {
            g_K[(size_t)(b*NN + ibase + i)*EE + o*DD + d] = __float2bfloat16_rn(ka[o]);
            g_Q[(size_t)(b*NN + ibase + i)*EE + o*DD + d] = __float2bfloat16_rn(qa[o]);
        }
    }

#pragma unroll
    for (int gr = 0; gr < 4; gr++) {
        float va[8];
#pragma unroll
        for (int o = 0; o < 8; o++) va[o] = sbv[gr*8 + o];
#pragma unroll
        for (int c = 0; c < CC; c++) {
            float xv = sX[c*256 + i];
#pragma unroll
            for (int o = 0; o < 8; o++)
                va[o] = fmaf(sWv[(gr*8 + o)*CC + c], xv, va[o]);
        }
#pragma unroll
        for (int o = 0; o < 8; o++)
            g_V[((size_t)(b*MM + (gr*8 + o)*DD + d))*NN + ibase + i] =
                __float2bfloat16_rn(va[o]);
    }
}

// ---------------------------------------------------------------------------
// QK kernel v2: 2D warp tiling (4 i-groups x 2 j-halves). A fragments stay
// persistent in registers (zero A crossbar); B reads halve to 64KB/jt.
// grid (32 i-tiles, 4 j-quarters, BB), 256 threads
// ---------------------------------------------------------------------------
#define QK_SM_K 0
#define QK_SM_Q 16384
#define QK_SM_P 32768                      // uint32[128][68]
#define QK_SMEM (32768 + 128*68*4)         // 67584

__global__ __launch_bounds__(256, 2) void rsa_qk_kernel()
{
    extern __shared__ char smem[];
    const uint32_t sb = smem_u32(smem);
    uint32_t* sP = (uint32_t*)(smem + QK_SM_P);
    const int tid  = threadIdx.x;
    const int wid  = tid >> 5, lane = tid & 31;
    const int g    = lane >> 2, q = lane & 3;
    const int b    = blockIdx.z, ibase = blockIdx.x * 128, quart = blockIdx.y;
    const int wi   = wid & 3;          // i-group: rows wi*32 .. +31
    const int wj   = wid >> 2;         // j-half:  cols wj*64 .. +63

    for (int f = tid; f < 1024; f += 256) {
        int r = f >> 3, c = f & 7;
        *(float4*)(smem + QK_SM_K + swoff(r, c)) =
            *(const float4*)(g_K + (size_t)(b*NN + ibase + r)*EE + c*8);
    }
    __syncthreads();

    // persistent A fragments: 2 i-subtiles x 4 k-steps
    uint32_t afr[2][4][4];
    {
        int sg = lane >> 3, rr = lane & 7;
#pragma unroll
        for (int it = 0; it < 2; it++) {
            int arow = wi*32 + it*16 + ((sg & 1) << 3) + rr;
#pragma unroll
            for (int ks = 0; ks < 4; ks++)
                ldm_x4(afr[it][ks], sb + QK_SM_K + swoff(arow, 2*ks + (sg >> 1)));
        }
    }

    const int brow = lane & 7, bco = lane >> 3;
    float rs[2][2] = {{0.f, 0.f}, {0.f, 0.f}};

    for (int jt = 0; jt < 8; jt++) {
        const int jb = quart*1024 + jt*128;
        __syncthreads();
        for (int f = tid; f < 1024; f += 256) {
            int r = f >> 3, c = f & 7;
            *(float4*)(smem + QK_SM_Q + swoff(r, c)) =
                *(const float4*)(g_Q + (size_t)(b*NN + jb + r)*EE + c*8);
        }
        __syncthreads();

#pragma unroll
        for (int f = 0; f < 8; f++) {
            uint32_t bfr[8];
            ldm_x4(bfr,     sb + QK_SM_Q + swoff(wj*64 + f*8 + brow, 0 + bco));
            ldm_x4(bfr + 4, sb + QK_SM_Q + swoff(wj*64 + f*8 + brow, 4 + bco));
#pragma unroll
            for (int it = 0; it < 2; it++) {
                float acc[4] = {0.f, 0.f, 0.f, 0.f};
                mma_bf16(acc, afr[it][0], bfr);
                mma_bf16(acc, afr[it][1], bfr + 2);
                mma_bf16(acc, afr[it][2], bfr + 4);
                mma_bf16(acc, afr[it][3], bfr + 6);
                float e0 = fast_exp(acc[0]), e1 = fast_exp(acc[1]);
                float e2 = fast_exp(acc[2]), e3 = fast_exp(acc[3]);
                rs[it][0] += e0 + e1; rs[it][1] += e2 + e3;
                __nv_bfloat162 h0 = __floats2bfloat162_rn(e0, e1);
                __nv_bfloat162 h1 = __floats2bfloat162_rn(e2, e3);
                sP[(wi*32 + it*16 + g    )*68 + wj*32 + f*4 + q] = *(uint32_t*)&h0;
                sP[(wi*32 + it*16 + g + 8)*68 + wj*32 + f*4 + q] = *(uint32_t*)&h1;
            }
        }
        __syncthreads();
        for (int f = tid; f < 8192; f += 256) {
            int r = f >> 6, c = f & 63;
            ((uint32_t*)(g_P + (size_t)(b*NN + ibase + r)*NN + jb))[c] = sP[r*68 + c];
        }
    }

    // rowsum: reduce over q lanes, then across the 2 wj warps via smem
#pragma unroll
    for (int it = 0; it < 2; it++)
#pragma unroll
        for (int h = 0; h < 2; h++) {
            rs[it][h] += __shfl_xor_sync(0xffffffffu, rs[it][h], 1);
            rs[it][h] += __shfl_xor_sync(0xffffffffu, rs[it][h], 2);
        }
    __syncthreads();                       // copy-out done; reuse sP as scratch
    float* sRed = (float*)sP;              // [128 rows][2 wj]
    if (q == 0) {
#pragma unroll
        for (int it = 0; it < 2; it++) {
            sRed[(wi*32 + it*16 + g    )*2 + wj] = rs[it][0];
            sRed[(wi*32 + it*16 + g + 8)*2 + wj] = rs[it][1];
        }
    }
    __syncthreads();
    if (tid < 128)
        g_rsum[(b*4 + quart)*NN + ibase + tid] = sRed[tid*2] + sRed[tid*2 + 1];
}

// ---------------------------------------------------------------------------
// PV kernel (R11-proven): warp tile 64i x 32m, k-step outer, double buffer.
// grid (32 i-tiles, 4 m-tiles, BB), 256 threads
// ---------------------------------------------------------------------------
#define PV_A0 0
#define PV_A1 16384
#define PV_B0 32768
#define PV_B1 49152
#define PV_SINV (128*132*4)                 // 67584 (sO occupies [0,67584))
#define PV_SMEM (PV_SINV + 512)

__global__ __launch_bounds__(256, 2) void rsa_pv_kernel(
    const float* __restrict__ x,
    const float* __restrict__ gamma,
    float* __restrict__ out)
{
    extern __shared__ char smem[];
    const uint32_t sb = smem_u32(smem);
    const int tid  = threadIdx.x;
    const int wid  = tid >> 5, lane = tid & 31;
    const int g    = lane >> 2, q = lane & 3;
    const int b    = blockIdx.z, ibase = blockIdx.x * 128, mbase = blockIdx.y * 128;
    const int wi   = wid & 1;          // i-half:    rows wi*64 .. +63
    const int wm   = wid >> 1;         // m-quarter: cols wm*32 .. +31

    const uint32_t smA[2] = { sb + PV_A0, sb + PV_A1 };
    const uint32_t smB[2] = { sb + PV_B0, sb + PV_B1 };

    auto load_chunk = [&](int c, int p) {
        const int jb = c * 64;
#pragma unroll
        for (int it = 0; it < 4; it++) {
            int f = it*256 + tid;
            int r = f >> 3, cc = f & 7;
            uint32_t off = swoff(r, cc);
            cpasync16(smA[p] + off, g_P + (size_t)(b*NN + ibase + r)*NN + jb + cc*8);
            cpasync16(smB[p] + off, g_V + (size_t)(b*MM + mbase + r)*NN + jb + cc*8);
        }
        asm volatile("cp.async.commit_group;" ::: "memory");
    };

    float acc[4][4][4];                 // [i-subtile][n-group][c-frag]
#pragma unroll
    for (int it = 0; it < 4; it++)
#pragma unroll
        for (int f = 0; f < 4; f++)
            acc[it][f][0] = acc[it][f][1] = acc[it][f][2] = acc[it][f][3] = 0.f;

    load_chunk(0, 0);

    const int sg = lane >> 3, rr = lane & 7;
    const int l16 = lane & 15;
    const int b2row = l16 & 7, b2half = l16 >> 3;

    for (int c = 0; c < 64; c++) {
        const int p = c & 1;
        if (c + 1 < 64) {
            load_chunk(c + 1, p ^ 1);
            asm volatile("cp.async.wait_group 1;" ::: "memory");
        } else {
            asm volatile("cp.async.wait_group 0;" ::: "memory");
        }
        __syncthreads();

#pragma unroll
        for (int ks = 0; ks < 4; ks++) {
            uint32_t afr[4][4];
#pragma unroll
            for (int it = 0; it < 4; it++) {
                int arow = wi*64 + it*16 + ((sg & 1) << 3) + rr;
                ldm_x4(afr[it], smA[p] + swoff(arow, 2*ks + (sg >> 1)));
            }
#pragma unroll
            for (int f = 0; f < 4; f++) {
                uint32_t bfr[2];
                ldm_x2(bfr, smB[p] + swoff(wm*32 + f*8 + b2row, 2*ks + b2half));
#pragma unroll
                for (int it = 0; it < 4; it++)
                    mma_bf16(acc[it][f], afr[it], bfr);
            }
        }
        __syncthreads();
    }

    // epilogue
    float* sO   = (float*)smem;                 // [128 m][132]
    float* sInv = (float*)(smem + PV_SINV);     // [128]
    if (tid < 128) {
        int i = ibase + tid;
        float rs = g_rsum[(b*4 + 0)*NN + i] + g_rsum[(b*4 + 1)*NN + i]
                 + g_rsum[(b*4 + 2)*NN + i] + g_rsum[(b*4 + 3)*NN + i];
        sInv[tid] = 1.0f / rs;
    }
#pragma unroll
    for (int it = 0; it < 4; it++) {
#pragma unroll
        for (int f = 0; f < 4; f++) {
            int m0 = wm*32 + f*8 + q*2;
            int il = wi*64 + it*16;
            sO[(m0    )*132 + il + g]     = acc[it][f][0];
            sO[(m0 + 1)*132 + il + g]     = acc[it][f][1];
            sO[(m0    )*132 + il + g + 8] = acc[it][f][2];
            sO[(m0 + 1)*132 + il + g + 8] = acc[it][f][3];
        }
    }
    __syncthreads();

    const float gm = gamma[0];
    for (int idx = tid; idx < 128*128; idx += 256) {
        int m = idx >> 7, i = idx & 127;
        size_t gi = (size_t)(b*MM + mbase + m)*NN + ibase + i;
        out[gi] = gm * x[gi] + sO[m*132 + i] * sInv[i];
    }
}

// ---------------------------------------------------------------------------
extern "C" void kernel_launch(void* const* d_in, const int* in_sizes, int n_in,
                              void* d_out, int out_size)
{
    const float* x     = (const float*)d_in[0];
    const float* Wk    = (const float*)d_in[1];
    const float* bk    = (const float*)d_in[2];
    const float* Wq    = (const float*)d_in[3];
    const float* bq    = (const float*)d_in[4];
    const float* Wv    = (const float*)d_in[5];
    const float* bv    = (const float*)d_in[6];
    const float* gamma = (const float*)d_in[7];
    float* out = (float*)d_out;

    cudaFuncSetAttribute(rsa_qk_kernel,
                         cudaFuncAttributeMaxDynamicSharedMemorySize, QK_SMEM);
    cudaFuncSetAttribute(rsa_pv_kernel,
                         cudaFuncAttributeMaxDynamicSharedMemorySize, PV_SMEM);

    rsa_proj_kernel<<<BB*DD*16, 256>>>(x, Wk, bk, Wq, bq, Wv, bv);

    dim3 gqk(32, 4, BB);
    rsa_qk_kernel<<<gqk, 256, QK_SMEM>>>();

    dim3 gpv(32, 4, BB);
    rsa_pv_kernel<<<gpv, 256, PV_SMEM>>>(x, gamma, out);
}

// round 14
// speedup vs baseline: 1.6951x; 1.0891x over previous
#include <cuda_runtime.h>
#include <cuda_bf16.h>
#include <cstdint>

#define BB 2
#define CC 32
#define DD 16
#define CKK 4
#define EE 64      // CKK*DD
#define MM 512     // CC*DD
#define NN 4096    // H*W

// ---------------- scratch (allocation-free device globals) -----------------
__device__ __align__(128) __nv_bfloat16 g_K[BB*NN*EE];         // [b][i][e]
__device__ __align__(128) __nv_bfloat16 g_Q[BB*NN*EE];         // [b][j][e]
__device__ __align__(128) __nv_bfloat16 g_V[BB*MM*NN];         // [b][m][j]
__device__ __align__(128) __nv_bfloat16 g_P[(size_t)BB*NN*NN]; // [b][i][j] 64MB
__device__ __align__(128) float g_rsum[BB*4*NN];               // [b][quarter][i]

// ---------------- helpers ---------------------------------------------------
__device__ __forceinline__ uint32_t smem_u32(const void* p) {
    uint32_t a;
    asm("{ .reg .u64 t; cvta.to.shared.u64 t, %1; cvt.u32.u64 %0, t; }"
        : "=r"(a) : "l"(p));
    return a;
}
// swizzled byte offset for (row, 16B-chunk) in a 128B-row tile
__device__ __forceinline__ uint32_t swoff(int r, int c) {
    return (uint32_t)(r * 128 + ((c ^ (r & 7)) << 4));
}
__device__ __forceinline__ void ldm_x4(uint32_t* r, uint32_t addr) {
    asm volatile("ldmatrix.sync.aligned.m8n8.x4.shared.b16 {%0,%1,%2,%3}, [%4];"
        : "=r"(r[0]), "=r"(r[1]), "=r"(r[2]), "=r"(r[3]) : "r"(addr));
}
__device__ __forceinline__ void ldm_x2(uint32_t* r, uint32_t addr) {
    asm volatile("ldmatrix.sync.aligned.m8n8.x2.shared.b16 {%0,%1}, [%2];"
        : "=r"(r[0]), "=r"(r[1]) : "r"(addr));
}
__device__ __forceinline__ void mma_bf16(float* c, const uint32_t* a, const uint32_t* b) {
    asm volatile("mma.sync.aligned.m16n8k16.row.col.f32.bf16.bf16.f32 "
        "{%0,%1,%2,%3}, {%4,%5,%6,%7}, {%8,%9}, {%0,%1,%2,%3};"
        : "+f"(c[0]), "+f"(c[1]), "+f"(c[2]), "+f"(c[3])
        : "r"(a[0]), "r"(a[1]), "r"(a[2]), "r"(a[3]), "r"(b[0]), "r"(b[1]));
}
__device__ __forceinline__ void cpasync16(uint32_t dst, const void* src) {
    asm volatile("cp.async.cg.shared.global [%0], [%1], 16;" :: "r"(dst), "l"(src));
}

// ---------------------------------------------------------------------------
// Projection v4 (R13-proven): float4 x-loads, low-register groups.
// grid BB*DD*16 (512 CTAs), 256 threads.
// ---------------------------------------------------------------------------
__global__ __launch_bounds__(256) void rsa_proj_kernel(
    const float* __restrict__ x,
    const float* __restrict__ Wk, const float* __restrict__ bk,
    const float* __restrict__ Wq, const float* __restrict__ bq,
    const float* __restrict__ Wv, const float* __restrict__ bv)
{
    __shared__ float sX[CC*256];
    __shared__ float sWk[CKK*CC], sWq[CKK*CC], sWv[CC*CC];
    __shared__ float sbk[CKK], sbq[CKK], sbv[CC];
    const int tid = threadIdx.x;
    for (int t = tid; t < CKK*CC; t += 256) { sWk[t] = Wk[t]; sWq[t] = Wq[t]; }
    for (int t = tid; t < CC*CC; t += 256) sWv[t] = Wv[t];
    if (tid < CKK) { sbk[tid] = bk[tid]; sbq[tid] = bq[tid]; }
    if (tid < CC)  sbv[tid] = bv[tid];

    const int blk   = blockIdx.x;
    const int chunk = blk & 15;
    const int d     = (blk >> 4) & 15;
    const int b     = blk >> 8;
    const int ibase = chunk * 256;

    {
        const int cg = tid >> 6;
        const int i4 = (tid & 63) << 2;
#pragma unroll
        for (int f = 0; f < 8; f++) {
            int c = f*4 + cg;
            *(float4*)&sX[c*256 + i4] =
                *(const float4*)&x[((size_t)(b*CC + c)*DD + d)*NN + ibase + i4];
        }
    }
    __syncthreads();

    const int i = tid;

    {
        float ka[CKK], qa[CKK];
#pragma unroll
        for (int o = 0; o < CKK; o++) { ka[o] = sbk[o]; qa[o] = sbq[o]; }
#pragma unroll
        for (int c = 0; c < CC; c++) {
            float xv = sX[c*256 + i];
#pragma unroll
            for (int o = 0; o < CKK; o++) {
                ka[o] = fmaf(sWk[o*CC + c], xv, ka[o]);
                qa[o] = fmaf(sWq[o*CC + c], xv, qa[o]);
            }
        }
#pragma unroll
        for (int o = 0; o < CKK; o++) {
            g_K[(size_t)(b*NN + ibase + i)*EE + o*DD + d] = __float2bfloat16_rn(ka[o]);
            g_Q[(size_t)(b*NN + ibase + i)*EE + o*DD + d] = __float2bfloat16_rn(qa[o]);
        }
    }

#pragma unroll
    for (int gr = 0; gr < 4; gr++) {
        float va[8];
#pragma unroll
        for (int o = 0; o < 8; o++) va[o] = sbv[gr*8 + o];
#pragma unroll
        for (int c = 0; c < CC; c++) {
            float xv = sX[c*256 + i];
#pragma unroll
            for (int o = 0; o < 8; o++)
                va[o] = fmaf(sWv[(gr*8 + o)*CC + c], xv, va[o]);
        }
#pragma unroll
        for (int o = 0; o < 8; o++)
            g_V[((size_t)(b*MM + (gr*8 + o)*DD + d))*NN + ibase + i] =
                __float2bfloat16_rn(va[o]);
    }
}

// ---------------------------------------------------------------------------
// QK kernel v3: 2D warp tiling, __expf (MUFU pipe), float4 copy-out.
// grid (32 i-tiles, 4 j-quarters, BB), 256 threads
// ---------------------------------------------------------------------------
#define QK_SM_K 0
#define QK_SM_Q 16384
#define QK_SM_P 32768                      // uint32[128][68] (272B rows, 16B-aligned)
#define QK_SMEM (32768 + 128*68*4)         // 67584

__global__ __launch_bounds__(256, 2) void rsa_qk_kernel()
{
    extern __shared__ char smem[];
    const uint32_t sb = smem_u32(smem);
    uint32_t* sP = (uint32_t*)(smem + QK_SM_P);
    const int tid  = threadIdx.x;
    const int wid  = tid >> 5, lane = tid & 31;
    const int g    = lane >> 2, q = lane & 3;
    const int b    = blockIdx.z, ibase = blockIdx.x * 128, quart = blockIdx.y;
    const int wi   = wid & 3;          // i-group: rows wi*32 .. +31
    const int wj   = wid >> 2;         // j-half:  cols wj*64 .. +63

    for (int f = tid; f < 1024; f += 256) {
        int r = f >> 3, c = f & 7;
        *(float4*)(smem + QK_SM_K + swoff(r, c)) =
            *(const float4*)(g_K + (size_t)(b*NN + ibase + r)*EE + c*8);
    }
    __syncthreads();

    // persistent A fragments: 2 i-subtiles x 4 k-steps
    uint32_t afr[2][4][4];
    {
        int sg = lane >> 3, rr = lane & 7;
#pragma unroll
        for (int it = 0; it < 2; it++) {
            int arow = wi*32 + it*16 + ((sg & 1) << 3) + rr;
#pragma unroll
            for (int ks = 0; ks < 4; ks++)
                ldm_x4(afr[it][ks], sb + QK_SM_K + swoff(arow, 2*ks + (sg >> 1)));
        }
    }

    const int brow = lane & 7, bco = lane >> 3;
    float rs[2][2] = {{0.f, 0.f}, {0.f, 0.f}};

    for (int jt = 0; jt < 8; jt++) {
        const int jb = quart*1024 + jt*128;
        __syncthreads();
        for (int f = tid; f < 1024; f += 256) {
            int r = f >> 3, c = f & 7;
            *(float4*)(smem + QK_SM_Q + swoff(r, c)) =
                *(const float4*)(g_Q + (size_t)(b*NN + jb + r)*EE + c*8);
        }
        __syncthreads();

#pragma unroll
        for (int f = 0; f < 8; f++) {
            uint32_t bfr[8];
            ldm_x4(bfr,     sb + QK_SM_Q + swoff(wj*64 + f*8 + brow, 0 + bco));
            ldm_x4(bfr + 4, sb + QK_SM_Q + swoff(wj*64 + f*8 + brow, 4 + bco));
#pragma unroll
            for (int it = 0; it < 2; it++) {
                float acc[4] = {0.f, 0.f, 0.f, 0.f};
                mma_bf16(acc, afr[it][0], bfr);
                mma_bf16(acc, afr[it][1], bfr + 2);
                mma_bf16(acc, afr[it][2], bfr + 4);
                mma_bf16(acc, afr[it][3], bfr + 6);
                float e0 = __expf(acc[0]), e1 = __expf(acc[1]);
                float e2 = __expf(acc[2]), e3 = __expf(acc[3]);
                rs[it][0] += e0 + e1; rs[it][1] += e2 + e3;
                __nv_bfloat162 h0 = __floats2bfloat162_rn(e0, e1);
                __nv_bfloat162 h1 = __floats2bfloat162_rn(e2, e3);
                sP[(wi*32 + it*16 + g    )*68 + wj*32 + f*4 + q] = *(uint32_t*)&h0;
                sP[(wi*32 + it*16 + g + 8)*68 + wj*32 + f*4 + q] = *(uint32_t*)&h1;
            }
        }
        __syncthreads();
        // float4 copy-out: 2048 float4 / 256 threads = 8 per thread
#pragma unroll
        for (int it = 0; it < 8; it++) {
            int idx = it*256 + tid;
            int r = idx >> 4, c = idx & 15;
            float4 v = *(float4*)&sP[r*68 + c*4];
            *(float4*)((char*)(g_P + (size_t)(b*NN + ibase + r)*NN + jb) + c*16) = v;
        }
    }

    // rowsum: reduce over q lanes, then across the 2 wj warps via smem
#pragma unroll
    for (int it = 0; it < 2; it++)
#pragma unroll
        for (int h = 0; h < 2; h++) {
            rs[it][h] += __shfl_xor_sync(0xffffffffu, rs[it][h], 1);
            rs[it][h] += __shfl_xor_sync(0xffffffffu, rs[it][h], 2);
        }
    __syncthreads();                       // copy-out done; reuse sP as scratch
    float* sRed = (float*)sP;              // [128 rows][2 wj]
    if (q == 0) {
#pragma unroll
        for (int it = 0; it < 2; it++) {
            sRed[(wi*32 + it*16 + g    )*2 + wj] = rs[it][0];
            sRed[(wi*32 + it*16 + g + 8)*2 + wj] = rs[it][1];
        }
    }
    __syncthreads();
    if (tid < 128)
        g_rsum[(b*4 + quart)*NN + ibase + tid] = sRed[tid*2] + sRed[tid*2 + 1];
}

// ---------------------------------------------------------------------------
// PV kernel: warp tile 64i x 32m, k-step outer, double buffer (R11-proven).
// Epilogue: sO stride 148 (16B-aligned + conflict-free), float4 streams.
// grid (32 i-tiles, 4 m-tiles, BB), 256 threads
// ---------------------------------------------------------------------------
#define PV_A0 0
#define PV_A1 16384
#define PV_B0 32768
#define PV_B1 49152
#define PV_SINV (128*148*4)                 // 75776 (sO occupies [0,75776))
#define PV_SMEM (PV_SINV + 512)

__global__ __launch_bounds__(256, 2) void rsa_pv_kernel(
    const float* __restrict__ x,
    const float* __restrict__ gamma,
    float* __restrict__ out)
{
    extern __shared__ char smem[];
    const uint32_t sb = smem_u32(smem);
    const int tid  = threadIdx.x;
    const int wid  = tid >> 5, lane = tid & 31;
    const int g    = lane >> 2, q = lane & 3;
    const int b    = blockIdx.z, ibase = blockIdx.x * 128, mbase = blockIdx.y * 128;
    const int wi   = wid & 1;          // i-half:    rows wi*64 .. +63
    const int wm   = wid >> 1;         // m-quarter: cols wm*32 .. +31

    const uint32_t smA[2] = { sb + PV_A0, sb + PV_A1 };
    const uint32_t smB[2] = { sb + PV_B0, sb + PV_B1 };

    auto load_chunk = [&](int c, int p) {
        const int jb = c * 64;
#pragma unroll
        for (int it = 0; it < 4; it++) {
            int f = it*256 + tid;
            int r = f >> 3, cc = f & 7;
            uint32_t off = swoff(r, cc);
            cpasync16(smA[p] + off, g_P + (size_t)(b*NN + ibase + r)*NN + jb + cc*8);
            cpasync16(smB[p] + off, g_V + (size_t)(b*MM + mbase + r)*NN + jb + cc*8);
        }
        asm volatile("cp.async.commit_group;" ::: "memory");
    };

    float acc[4][4][4];                 // [i-subtile][n-group][c-frag]
#pragma unroll
    for (int it = 0; it < 4; it++)
#pragma unroll
        for (int f = 0; f < 4; f++)
            acc[it][f][0] = acc[it][f][1] = acc[it][f][2] = acc[it][f][3] = 0.f;

    load_chunk(0, 0);

    const int sg = lane >> 3, rr = lane & 7;
    const int l16 = lane & 15;
    const int b2row = l16 & 7, b2half = l16 >> 3;

    for (int c = 0; c < 64; c++) {
        const int p = c & 1;
        if (c + 1 < 64) {
            load_chunk(c + 1, p ^ 1);
            asm volatile("cp.async.wait_group 1;" ::: "memory");
        } else {
            asm volatile("cp.async.wait_group 0;" ::: "memory");
        }
        __syncthreads();

#pragma unroll
        for (int ks = 0; ks < 4; ks++) {
            uint32_t afr[4][4];
#pragma unroll
            for (int it = 0; it < 4; it++) {
                int arow = wi*64 + it*16 + ((sg & 1) << 3) + rr;
                ldm_x4(afr[it], smA[p] + swoff(arow, 2*ks + (sg >> 1)));
            }
#pragma unroll
            for (int f = 0; f < 4; f++) {
                uint32_t bfr[2];
                ldm_x2(bfr, smB[p] + swoff(wm*32 + f*8 + b2row, 2*ks + b2half));
#pragma unroll
                for (int it = 0; it < 4; it++)
                    mma_bf16(acc[it][f], afr[it], bfr);
            }
        }
        __syncthreads();
    }

    // epilogue
    float* sO   = (float*)smem;                 // [128 m][148]
    float* sInv = (float*)(smem + PV_SINV);     // [128]
    if (tid < 128) {
        int i = ibase + tid;
        float rs = g_rsum[(b*4 + 0)*NN + i] + g_rsum[(b*4 + 1)*NN + i]
                 + g_rsum[(b*4 + 2)*NN + i] + g_rsum[(b*4 + 3)*NN + i];
        sInv[tid] = 1.0f / rs;
    }
#pragma unroll
    for (int it = 0; it < 4; it++) {
#pragma unroll
        for (int f = 0; f < 4; f++) {
            int m0 = wm*32 + f*8 + q*2;
            int il = wi*64 + it*16;
            sO[(m0    )*148 + il + g]     = acc[it][f][0];
            sO[(m0 + 1)*148 + il + g]     = acc[it][f][1];
            sO[(m0    )*148 + il + g + 8] = acc[it][f][2];
            sO[(m0 + 1)*148 + il + g + 8] = acc[it][f][3];
        }
    }
    __syncthreads();

    const float gm = gamma[0];
#pragma unroll
    for (int it = 0; it < 16; it++) {
        int idx = it*256 + tid;            // 0..4095 float4s
        int m = idx >> 5, i4 = (idx & 31) << 2;
        size_t gi = (size_t)(b*MM + mbase + m)*NN + ibase + i4;
        float4 o  = *(float4*)&sO[m*148 + i4];
        float4 xv = *(const float4*)&x[gi];
        float4 iv = *(float4*)&sInv[i4];
        float4 r;
        r.x = gm*xv.x + o.x*iv.x;
        r.y = gm*xv.y + o.y*iv.y;
        r.z = gm*xv.z + o.z*iv.z;
        r.w = gm*xv.w + o.w*iv.w;
        *(float4*)&out[gi] = r;
    }
}

// ---------------------------------------------------------------------------
extern "C" void kernel_launch(void* const* d_in, const int* in_sizes, int n_in,
                              void* d_out, int out_size)
{
    const float* x     = (const float*)d_in[0];
    const float* Wk    = (const float*)d_in[1];
    const float* bk    = (const float*)d_in[2];
    const float* Wq    = (const float*)d_in[3];
    const float* bq    = (const float*)d_in[4];
    const float* Wv    = (const float*)d_in[5];
    const float* bv    = (const float*)d_in[6];
    const float* gamma = (const float*)d_in[7];
    float* out = (float*)d_out;

    cudaFuncSetAttribute(rsa_qk_kernel,
                         cudaFuncAttributeMaxDynamicSharedMemorySize, QK_SMEM);
    cudaFuncSetAttribute(rsa_pv_kernel,
                         cudaFuncAttributeMaxDynamicSharedMemorySize, PV_SMEM);

    rsa_proj_kernel<<<BB*DD*16, 256>>>(x, Wk, bk, Wq, bq, Wv, bv);

    dim3 gqk(32, 4, BB);
    rsa_qk_kernel<<<gqk, 256, QK_SMEM>>>();

    dim3 gpv(32, 4, BB);
    rsa_pv_kernel<<<gpv, 256, PV_SMEM>>>(x, gamma, out);
}

// round 16
// speedup vs baseline: 1.7694x; 1.0439x over previous
#include <cuda_runtime.h>
#include <cuda_bf16.h>
#include <cstdint>

#define BB 2
#define CC 32
#define DD 16
#define CKK 4
#define EE 64      // CKK*DD
#define MM 512     // CC*DD
#define NN 4096    // H*W

// ---------------- scratch (allocation-free device globals) -----------------
__device__ __align__(128) __nv_bfloat16 g_K[BB*NN*EE];         // [b][i][e]
__device__ __align__(128) __nv_bfloat16 g_Q[BB*NN*EE];         // [b][j][e]
__device__ __align__(128) __nv_bfloat16 g_V[BB*MM*NN];         // [b][m][j]
__device__ __align__(128) __nv_bfloat16 g_P[(size_t)BB*NN*NN]; // [b][i][j] 64MB
__device__ __align__(128) float g_rsum[BB*4*NN];               // [b][quarter][i]

// ---------------- helpers ---------------------------------------------------
__device__ __forceinline__ uint32_t smem_u32(const void* p) {
    uint32_t a;
    asm("{ .reg .u64 t; cvta.to.shared.u64 t, %1; cvt.u32.u64 %0, t; }"
        : "=r"(a) : "l"(p));
    return a;
}
// swizzled byte offset for (row, 16B-chunk) in a 128B-row tile
__device__ __forceinline__ uint32_t swoff(int r, int c) {
    return (uint32_t)(r * 128 + ((c ^ (r & 7)) << 4));
}
__device__ __forceinline__ void ldm_x4(uint32_t* r, uint32_t addr) {
    asm volatile("ldmatrix.sync.aligned.m8n8.x4.shared.b16 {%0,%1,%2,%3}, [%4];"
        : "=r"(r[0]), "=r"(r[1]), "=r"(r[2]), "=r"(r[3]) : "r"(addr));
}
__device__ __forceinline__ void mma_bf16(float* c, const uint32_t* a, const uint32_t* b) {
    asm volatile("mma.sync.aligned.m16n8k16.row.col.f32.bf16.bf16.f32 "
        "{%0,%1,%2,%3}, {%4,%5,%6,%7}, {%8,%9}, {%0,%1,%2,%3};"
        : "+f"(c[0]), "+f"(c[1]), "+f"(c[2]), "+f"(c[3])
        : "r"(a[0]), "r"(a[1]), "r"(a[2]), "r"(a[3]), "r"(b[0]), "r"(b[1]));
}
__device__ __forceinline__ void cpasync16(uint32_t dst, const void* src) {
    asm volatile("cp.async.cg.shared.global [%0], [%1], 16;" :: "r"(dst), "l"(src));
}
#define CP_COMMIT() asm volatile("cp.async.commit_group;" ::: "memory")
#define CP_WAIT(n)  asm volatile("cp.async.wait_group %0;" :: "n"(n) : "memory")

// ---------------------------------------------------------------------------
// Projection v4 (R13-proven): float4 x-loads, low-register groups.
// grid BB*DD*16 (512 CTAs), 256 threads.
// ---------------------------------------------------------------------------
__global__ __launch_bounds__(256) void rsa_proj_kernel(
    const float* __restrict__ x,
    const float* __restrict__ Wk, const float* __restrict__ bk,
    const float* __restrict__ Wq, const float* __restrict__ bq,
    const float* __restrict__ Wv, const float* __restrict__ bv)
{
    __shared__ float sX[CC*256];
    __shared__ float sWk[CKK*CC], sWq[CKK*CC], sWv[CC*CC];
    __shared__ float sbk[CKK], sbq[CKK], sbv[CC];
    const int tid = threadIdx.x;
    for (int t = tid; t < CKK*CC; t += 256) { sWk[t] = Wk[t]; sWq[t] = Wq[t]; }
    for (int t = tid; t < CC*CC; t += 256) sWv[t] = Wv[t];
    if (tid < CKK) { sbk[tid] = bk[tid]; sbq[tid] = bq[tid]; }
    if (tid < CC)  sbv[tid] = bv[tid];

    const int blk   = blockIdx.x;
    const int chunk = blk & 15;
    const int d     = (blk >> 4) & 15;
    const int b     = blk >> 8;
    const int ibase = chunk * 256;

    {
        const int cg = tid >> 6;
        const int i4 = (tid & 63) << 2;
#pragma unroll
        for (int f = 0; f < 8; f++) {
            int c = f*4 + cg;
            *(float4*)&sX[c*256 + i4] =
                *(const float4*)&x[((size_t)(b*CC + c)*DD + d)*NN + ibase + i4];
        }
    }
    __syncthreads();

    const int i = tid;

    {
        float ka[CKK], qa[CKK];
#pragma unroll
        for (int o = 0; o < CKK; o++) { ka[o] = sbk[o]; qa[o] = sbq[o]; }
#pragma unroll
        for (int c = 0; c < CC; c++) {
            float xv = sX[c*256 + i];
#pragma unroll
            for (int o = 0; o < CKK; o++) {
                ka[o] = fmaf(sWk[o*CC + c], xv, ka[o]);
                qa[o] = fmaf(sWq[o*CC + c], xv, qa[o]);
            }
        }
#pragma unroll
        for (int o = 0; o < CKK; o++) {
            g_K[(size_t)(b*NN + ibase + i)*EE + o*DD + d] = __float2bfloat16_rn(ka[o]);
            g_Q[(size_t)(b*NN + ibase + i)*EE + o*DD + d] = __float2bfloat16_rn(qa[o]);
        }
    }

#pragma unroll
    for (int gr = 0; gr < 4; gr++) {
        float va[8];
#pragma unroll
        for (int o = 0; o < 8; o++) va[o] = sbv[gr*8 + o];
#pragma unroll
        for (int c = 0; c < CC; c++) {
            float xv = sX[c*256 + i];
#pragma unroll
            for (int o = 0; o < 8; o++)
                va[o] = fmaf(sWv[(gr*8 + o)*CC + c], xv, va[o]);
        }
#pragma unroll
        for (int o = 0; o < 8; o++)
            g_V[((size_t)(b*MM + (gr*8 + o)*DD + d))*NN + ibase + i] =
                __float2bfloat16_rn(va[o]);
    }
}

// ---------------------------------------------------------------------------
// QK kernel v4: 2D warp tiling, __expf, float4 copy-out,
// cp.async DOUBLE-BUFFERED Q tiles (load jt+1 overlaps compute jt).
// grid (32 i-tiles, 4 j-quarters, BB), 256 threads
// ---------------------------------------------------------------------------
#define QK_SM_K  0
#define QK_SM_Q0 16384
#define QK_SM_Q1 32768
#define QK_SM_P  49152                     // uint32[128][68] (272B rows)
#define QK_SMEM  (49152 + 128*68*4)        // 83968

__global__ __launch_bounds__(256, 2) void rsa_qk_kernel()
{
    extern __shared__ char smem[];
    const uint32_t sb = smem_u32(smem);
    uint32_t* sP = (uint32_t*)(smem + QK_SM_P);
    const int tid  = threadIdx.x;
    const int wid  = tid >> 5, lane = tid & 31;
    const int g    = lane >> 2, q = lane & 3;
    const int b    = blockIdx.z, ibase = blockIdx.x * 128, quart = blockIdx.y;
    const int wi   = wid & 3;          // i-group: rows wi*32 .. +31
    const int wj   = wid >> 2;         // j-half:  cols wj*64 .. +63

    const uint32_t smQ[2] = { sb + QK_SM_Q0, sb + QK_SM_Q1 };

    auto load_Q = [&](int jt, int p) {
        const int jb = quart*1024 + jt*128;
#pragma unroll
        for (int it = 0; it < 4; it++) {
            int f = it*256 + tid;
            int r = f >> 3, c = f & 7;
            cpasync16(smQ[p] + swoff(r, c),
                      g_Q + (size_t)(b*NN + jb + r)*EE + c*8);
        }
        CP_COMMIT();
    };

    load_Q(0, 0);

    for (int f = tid; f < 1024; f += 256) {
        int r = f >> 3, c = f & 7;
        *(float4*)(smem + QK_SM_K + swoff(r, c)) =
            *(const float4*)(g_K + (size_t)(b*NN + ibase + r)*EE + c*8);
    }
    __syncthreads();

    // persistent A fragments: 2 i-subtiles x 4 k-steps
    uint32_t afr[2][4][4];
    {
        int sg = lane >> 3, rr = lane & 7;
#pragma unroll
        for (int it = 0; it < 2; it++) {
            int arow = wi*32 + it*16 + ((sg & 1) << 3) + rr;
#pragma unroll
            for (int ks = 0; ks < 4; ks++)
                ldm_x4(afr[it][ks], sb + QK_SM_K + swoff(arow, 2*ks + (sg >> 1)));
        }
    }

    const int brow = lane & 7, bco = lane >> 3;
    float rs[2][2] = {{0.f, 0.f}, {0.f, 0.f}};

    for (int jt = 0; jt < 8; jt++) {
        const int p  = jt & 1;
        const int jb = quart*1024 + jt*128;
        __syncthreads();                   // compute jt-1 (reads Q[p^1]) done
        if (jt + 1 < 8) { load_Q(jt + 1, p ^ 1); CP_WAIT(1); }
        else            { CP_WAIT(0); }
        __syncthreads();                   // Q[p] visible to all

#pragma unroll
        for (int f = 0; f < 8; f++) {
            uint32_t bfr[8];
            ldm_x4(bfr,     smQ[p] + swoff(wj*64 + f*8 + brow, 0 + bco));
            ldm_x4(bfr + 4, smQ[p] + swoff(wj*64 + f*8 + brow, 4 + bco));
#pragma unroll
            for (int it = 0; it < 2; it++) {
                float acc[4] = {0.f, 0.f, 0.f, 0.f};
                mma_bf16(acc, afr[it][0], bfr);
                mma_bf16(acc, afr[it][1], bfr + 2);
                mma_bf16(acc, afr[it][2], bfr + 4);
                mma_bf16(acc, afr[it][3], bfr + 6);
                float e0 = __expf(acc[0]), e1 = __expf(acc[1]);
                float e2 = __expf(acc[2]), e3 = __expf(acc[3]);
                rs[it][0] += e0 + e1; rs[it][1] += e2 + e3;
                __nv_bfloat162 h0 = __floats2bfloat162_rn(e0, e1);
                __nv_bfloat162 h1 = __floats2bfloat162_rn(e2, e3);
                sP[(wi*32 + it*16 + g    )*68 + wj*32 + f*4 + q] = *(uint32_t*)&h0;
                sP[(wi*32 + it*16 + g + 8)*68 + wj*32 + f*4 + q] = *(uint32_t*)&h1;
            }
        }
        __syncthreads();
        // float4 copy-out: 2048 float4 / 256 threads = 8 per thread
#pragma unroll
        for (int it = 0; it < 8; it++) {
            int idx = it*256 + tid;
            int r = idx >> 4, c = idx & 15;
            float4 v = *(float4*)&sP[r*68 + c*4];
            *(float4*)((char*)(g_P + (size_t)(b*NN + ibase + r)*NN + jb) + c*16) = v;
        }
    }

    // rowsum: reduce over q lanes, then across the 2 wj warps via smem
#pragma unroll
    for (int it = 0; it < 2; it++)
#pragma unroll
        for (int h = 0; h < 2; h++) {
            rs[it][h] += __shfl_xor_sync(0xffffffffu, rs[it][h], 1);
            rs[it][h] += __shfl_xor_sync(0xffffffffu, rs[it][h], 2);
        }
    __syncthreads();                       // copy-out done; reuse sP as scratch
    float* sRed = (float*)sP;              // [128 rows][2 wj]
    if (q == 0) {
#pragma unroll
        for (int it = 0; it < 2; it++) {
            sRed[(wi*32 + it*16 + g    )*2 + wj] = rs[it][0];
            sRed[(wi*32 + it*16 + g + 8)*2 + wj] = rs[it][1];
        }
    }
    __syncthreads();
    if (tid < 128)
        g_rsum[(b*4 + quart)*NN + ibase + tid] = sRed[tid*2] + sRed[tid*2 + 1];
}

// ---------------------------------------------------------------------------
// PV kernel: warp tile 64i x 32m, k-step outer; 3-STAGE ring with lead-2
// prefetch (wait_group returns immediately); B ldmatrix merged to x4 pairs.
// grid (32 i-tiles, 4 m-tiles, BB), 256 threads
// ---------------------------------------------------------------------------
#define PV_STAGE 32768                      // A(16K) + B(16K) per stage
#define PV_SINV  (3*PV_STAGE)               // 98304 (sO [0,75776) fits below)
#define PV_SMEM  (PV_SINV + 512)

__global__ __launch_bounds__(256, 2) void rsa_pv_kernel(
    const float* __restrict__ x,
    const float* __restrict__ gamma,
    float* __restrict__ out)
{
    extern __shared__ char smem[];
    const uint32_t sb = smem_u32(smem);
    const int tid  = threadIdx.x;
    const int wid  = tid >> 5, lane = tid & 31;
    const int g    = lane >> 2, q = lane & 3;
    const int b    = blockIdx.z, ibase = blockIdx.x * 128, mbase = blockIdx.y * 128;
    const int wi   = wid & 1;          // i-half:    rows wi*64 .. +63
    const int wm   = wid >> 1;         // m-quarter: cols wm*32 .. +31

    auto load_chunk = [&](int c, int s) {
        const int jb = c * 64;
        const uint32_t sA = sb + s*PV_STAGE;
        const uint32_t sB = sA + 16384;
#pragma unroll
        for (int it = 0; it < 4; it++) {
            int f = it*256 + tid;
            int r = f >> 3, cc = f & 7;
            uint32_t off = swoff(r, cc);
            cpasync16(sA + off, g_P + (size_t)(b*NN + ibase + r)*NN + jb + cc*8);
            cpasync16(sB + off, g_V + (size_t)(b*MM + mbase + r)*NN + jb + cc*8);
        }
        CP_COMMIT();
    };

    float acc[4][4][4];                 // [i-subtile][n-group][c-frag]
#pragma unroll
    for (int it = 0; it < 4; it++)
#pragma unroll
        for (int f = 0; f < 4; f++)
            acc[it][f][0] = acc[it][f][1] = acc[it][f][2] = acc[it][f][3] = 0.f;

    load_chunk(0, 0);
    load_chunk(1, 1);

    const int sg = lane >> 3, rr = lane & 7;
    // merged-B ldm_x4 addressing (2 n-groups per load)
    const int b4row = ((lane >> 4) << 3) + (lane & 7);
    const int b4col = (lane >> 3) & 1;

    for (int c = 0; c < 64; c++) {
        const int s = c % 3;
        __syncthreads();                   // compute c-1 done -> stage (c+2)%3 free
        if (c + 2 < 64) { load_chunk(c + 2, (c + 2) % 3); CP_WAIT(2); }
        else if (c + 1 < 64) { CP_WAIT(1); }
        else { CP_WAIT(0); }
        __syncthreads();                   // stage s (chunk c) visible

        const uint32_t sA = sb + s*PV_STAGE;
        const uint32_t sB = sA + 16384;

#pragma unroll
        for (int ks = 0; ks < 4; ks++) {
            uint32_t afr[4][4];
#pragma unroll
            for (int it = 0; it < 4; it++) {
                int arow = wi*64 + it*16 + ((sg & 1) << 3) + rr;
                ldm_x4(afr[it], sA + swoff(arow, 2*ks + (sg >> 1)));
            }
#pragma unroll
            for (int fp = 0; fp < 2; fp++) {
                uint32_t bfr[4];
                ldm_x4(bfr, sB + swoff(wm*32 + fp*16 + b4row, 2*ks + b4col));
#pragma unroll
                for (int it = 0; it < 4; it++) {
                    mma_bf16(acc[it][2*fp    ], afr[it], bfr);
                    mma_bf16(acc[it][2*fp + 1], afr[it], bfr + 2);
                }
            }
        }
    }
    __syncthreads();                       // all computes done before smem reuse

    // epilogue
    float* sO   = (float*)smem;                 // [128 m][148]
    float* sInv = (float*)(smem + PV_SINV);     // [128]
    if (tid < 128) {
        int i = ibase + tid;
        float rs = g_rsum[(b*4 + 0)*NN + i] + g_rsum[(b*4 + 1)*NN + i]
                 + g_rsum[(b*4 + 2)*NN + i] + g_rsum[(b*4 + 3)*NN + i];
        sInv[tid] = 1.0f / rs;
    }
#pragma unroll
    for (int it = 0; it < 4; it++) {
#pragma unroll
        for (int f = 0; f < 4; f++) {
            int m0 = wm*32 + f*8 + q*2;
            int il = wi*64 + it*16;
            sO[(m0    )*148 + il + g]     = acc[it][f][0];
            sO[(m0 + 1)*148 + il + g]     = acc[it][f][1];
            sO[(m0    )*148 + il + g + 8] = acc[it][f][2];
            sO[(m0 + 1)*148 + il + g + 8] = acc[it][f][3];
        }
    }
    __syncthreads();

    const float gm = gamma[0];
#pragma unroll
    for (int it = 0; it < 16; it++) {
        int idx = it*256 + tid;            // 0..4095 float4s
        int m = idx >> 5, i4 = (idx & 31) << 2;
        size_t gi = (size_t)(b*MM + mbase + m)*NN + ibase + i4;
        float4 o  = *(float4*)&sO[m*148 + i4];
        float4 xv = *(const float4*)&x[gi];
        float4 iv = *(float4*)&sInv[i4];
        float4 r;
        r.x = gm*xv.x + o.x*iv.x;
        r.y = gm*xv.y + o.y*iv.y;
        r.z = gm*xv.z + o.z*iv.z;
        r.w = gm*xv.w + o.w*iv.w;
        *(float4*)&out[gi] = r;
    }
}

// ---------------------------------------------------------------------------
extern "C" void kernel_launch(void* const* d_in, const int* in_sizes, int n_in,
                              void* d_out, int out_size)
{
    const float* x     = (const float*)d_in[0];
    const float* Wk    = (const float*)d_in[1];
    const float* bk    = (const float*)d_in[2];
    const float* Wq    = (const float*)d_in[3];
    const float* bq    = (const float*)d_in[4];
    const float* Wv    = (const float*)d_in[5];
    const float* bv    = (const float*)d_in[6];
    const float* gamma = (const float*)d_in[7];
    float* out = (float*)d_out;

    cudaFuncSetAttribute(rsa_qk_kernel,
                         cudaFuncAttributeMaxDynamicSharedMemorySize, QK_SMEM);
    cudaFuncSetAttribute(rsa_pv_kernel,
                         cudaFuncAttributeMaxDynamicSharedMemorySize, PV_SMEM);

    rsa_proj_kernel<<<BB*DD*16, 256>>>(x, Wk, bk, Wq, bq, Wv, bv);

    dim3 gqk(32, 4, BB);
    rsa_qk_kernel<<<gqk, 256, QK_SMEM>>>();

    dim3 gpv(32, 4, BB);
    rsa_pv_kernel<<<gpv, 256, PV_SMEM>>>(x, gamma, out);
}